// round 8
// baseline (speedup 1.0000x reference)
#include <cuda_runtime.h>
#include <cstdint>

// ---------------------------------------------------------------------------
// STGN_LSTM == pointwise map of X[:,4,:].
// r7 diagnosis: MUFU ~69-77% but dur = MUFU_model * 1.30 -- multi-CTA spread
// from front-batched per-thread LDGs (L1tex queue contention), per the B300
// spread model. Fix: NO per-thread LDG at all.
//   * prep kernel (1 CTA) fuses weights/biases -> __device__ table (once)
//   * main kernel pulls its X slab + the table via cp.async.bulk (async proxy)
//   * 1 row/thread, 2 units per f32x2 op: weight pairs are naturally packed
//     (ulonglong2 from LDS.128, zero duplication movs)
// MUFU stays 3 tanh values per (row,unit) -- the binding pipe.
// ---------------------------------------------------------------------------

typedef unsigned long long u64;

#define ROWS_PER_CTA 128
#define X_SLAB_BYTES (ROWS_PER_CTA * 15 * 4)      // 7680
#define TAB_FLOATS   516                           // 32 pairs*16 + cb + pad
#define TAB_BYTES    (TAB_FLOATS * 4)              // 2064 (mult of 16)

__device__ float g_tab[TAB_FLOATS];

static __device__ __forceinline__ float tanh_mufu(float x) {
    float y; asm("tanh.approx.f32 %0, %1;" : "=f"(y) : "f"(x)); return y;
}
static __device__ __forceinline__ u64 pk(float lo, float hi) {
    u64 r; asm("mov.b64 %0, {%1, %2};" : "=l"(r) : "f"(lo), "f"(hi)); return r;
}
static __device__ __forceinline__ void upk(float& lo, float& hi, u64 v) {
    asm("mov.b64 {%0, %1}, %2;" : "=f"(lo), "=f"(hi) : "l"(v));
}
static __device__ __forceinline__ u64 fma2(u64 a, u64 b, u64 c) {
    u64 d; asm("fma.rn.f32x2 %0, %1, %2, %3;" : "=l"(d) : "l"(a), "l"(b), "l"(c));
    return d;
}
static __device__ __forceinline__ u64 mul2(u64 a, u64 b) {
    u64 d; asm("mul.rn.f32x2 %0, %1, %2;" : "=l"(d) : "l"(a), "l"(b)); return d;
}
static __device__ __forceinline__ u64 tanh2_mufu(u64 v) {
    float a, b; upk(a, b, v);
    return pk(tanh_mufu(a), tanh_mufu(b));
}
static __device__ __forceinline__ uint32_t smem_u32(const void* p) {
    uint32_t a;
    asm("{ .reg .u64 t; cvta.to.shared.u64 t, %1; cvt.u32.u64 %0, t; }" : "=r"(a) : "l"(p));
    return a;
}

// ---- prep: fuse weights/biases into packed pair table (runs once, 1 CTA) ----
__global__ void prep_kernel(const float* __restrict__ Wix, const float* __restrict__ Wix_b,
                            const float* __restrict__ Wih_b, const float* __restrict__ bi,
                            const float* __restrict__ WTx, const float* __restrict__ WTx_b,
                            const float* __restrict__ WTh_b,
                            const float* __restrict__ WTt, const float* __restrict__ WTt_b,
                            const float* __restrict__ bT,
                            const float* __restrict__ clsw, const float* __restrict__ clsb) {
    const int p = threadIdx.x;          // pair id, 0..31
    if (p < 32) {
        float* d = g_tab + p * 16;
#pragma unroll
        for (int e = 0; e < 2; e++) {
            const int n = 2 * p + e;
            d[0 + e]  = 0.5f * Wix[2 * n];                              // A
            d[2 + e]  = 0.5f * Wix[2 * n + 1];                          // B
            d[4 + e]  = 0.5f * (Wih_b[n] + Wix_b[n] + bi[n]);           // C
            d[6 + e]  = 0.5f * WTt[n];                                  // D
            d[8 + e]  = 0.5f * WTx[2 * n];                              // E
            d[10 + e] = 0.5f * WTx[2 * n + 1];                          // F
            d[12 + e] = 0.5f * (WTh_b[n] + WTx_b[n] + WTt_b[n] + bT[n]);// G
            d[14 + e] = clsw[n];                                        // W
        }
    }
    if (p == 32) g_tab[512] = clsb[0];
}

// ---- main ----
__global__ void __launch_bounds__(ROWS_PER_CTA)
stgn_kernel(const float* __restrict__ X, float* __restrict__ out) {
    __shared__ alignas(16) float Xs[ROWS_PER_CTA * 15];
    __shared__ alignas(16) float Tb[TAB_FLOATS];
    __shared__ alignas(8)  u64 mbar;

    const int tid = threadIdx.x;

    if (tid == 0) {
        asm volatile("mbarrier.init.shared.b64 [%0], 1;"
                     :: "r"(smem_u32(&mbar)) : "memory");
    }
    __syncthreads();
    if (tid == 0) {
        const uint32_t mb = smem_u32(&mbar);
        asm volatile("mbarrier.arrive.expect_tx.shared.b64 _, [%0], %1;"
                     :: "r"(mb), "r"((uint32_t)(X_SLAB_BYTES + TAB_BYTES)) : "memory");
        asm volatile("cp.async.bulk.shared::cta.global.mbarrier::complete_tx::bytes "
                     "[%0], [%1], %2, [%3];"
                     :: "r"(smem_u32(Xs)),
                        "l"(X + (size_t)blockIdx.x * (ROWS_PER_CTA * 15)),
                        "r"((uint32_t)X_SLAB_BYTES), "r"(mb) : "memory");
        asm volatile("cp.async.bulk.shared::cta.global.mbarrier::complete_tx::bytes "
                     "[%0], [%1], %2, [%3];"
                     :: "r"(smem_u32(Tb)), "l"((const float*)g_tab),
                        "r"((uint32_t)TAB_BYTES), "r"(mb) : "memory");
    }
    // wait (parity 0)
    {
        const uint32_t mb = smem_u32(&mbar);
        uint32_t done;
        asm volatile("{\n\t.reg .pred p;\n\t"
            "mbarrier.try_wait.parity.acquire.cta.shared::cta.b64 p, [%1], 0;\n\t"
            "selp.b32 %0, 1, 0, p;\n\t}" : "=r"(done) : "r"(mb) : "memory");
        if (!done) {
            asm volatile("{\n\t.reg .pred P1;\n\t"
                "WL_%=:\n\t"
                "mbarrier.try_wait.parity.acquire.cta.shared::cta.b64 P1, [%0], 0, 0x989680;\n\t"
                "@P1 bra.uni WD_%=;\n\t"
                "bra.uni WL_%=;\n\t"
                "WD_%=:\n\t}" :: "r"(mb) : "memory");
        }
    }

    // row-local inputs (x at t=4: offsets 12..14 of the 15-float row)
    const float x0 = Xs[tid * 15 + 12];
    const float x1 = Xs[tid * 15 + 13];
    const float dt = Xs[tid * 15 + 14];

    const u64 x0p = pk(x0, x0);
    const u64 x1p = pk(x1, x1);
    const u64 dtp = pk(dt, dt);
    const u64 dth = pk(0.5f * dt, 0.5f * dt);
    const u64 h05 = pk(0.5f, 0.5f);

    // tanh(x) ~= x*P(x^2) on [-1,1] (deg-4 Chebyshev in s, ~5e-5 abs)
    const u64 P0 = pk(0.9999900f, 0.9999900f);
    const u64 P1c = pk(-0.3322640f, -0.3322640f);
    const u64 P2 = pk(0.1274560f, 0.1274560f);
    const u64 P3 = pk(-0.0412160f, -0.0412160f);
    const u64 P4 = pk(0.0076800f, 0.0076800f);

    u64 lg = pk(0.0f, 0.0f);
    const ulonglong2* TbU = (const ulonglong2*)Tb;

#pragma unroll 8
    for (int p = 0; p < 32; p++) {
        const ulonglong2 w0 = TbU[4 * p + 0];   // (Ap, Bp)
        const ulonglong2 w1 = TbU[4 * p + 1];   // (Cp, Dp)
        const ulonglong2 w2 = TbU[4 * p + 2];   // (Ep, Fp)
        const ulonglong2 w3 = TbU[4 * p + 3];   // (Gp, Wp)

        const u64 z1 = fma2(w0.x, x0p, fma2(w0.y, x1p, w1.x));              // 0.5*zi
        const u64 z2 = fma2(w2.x, x0p, fma2(w2.y, x1p, fma2(w1.y, dtp, w3.x))); // 0.5*zT

        const u64 t1 = tanh2_mufu(z1);
        const u64 t2 = tanh2_mufu(z2);
        const u64 ig = fma2(t1, h05, h05);      // sig(zi)
        const u64 ta = fma2(t2, dth, dth);      // sig(zT)*dt
        const u64 uu = tanh2_mufu(ta);
        const u64 cc = mul2(ig, uu);            // |cc| <= 1

        const u64 s = mul2(cc, cc);
        u64 q = fma2(P4, s, P3);
        q = fma2(q, s, P2);
        q = fma2(q, s, P1c);
        q = fma2(q, s, P0);
        const u64 h = mul2(q, cc);

        lg = fma2(h, w3.y, lg);
    }

    float lgA, lgB; upk(lgA, lgB, lg);
    const float logit = lgA + lgB + Tb[512];
    out[(size_t)blockIdx.x * ROWS_PER_CTA + tid] =
        __fdividef(1.0f, 1.0f + __expf(-logit));
}

extern "C" void kernel_launch(void* const* d_in, const int* in_sizes, int n_in,
                              void* d_out, int out_size) {
    const float* X      = (const float*)d_in[0];
    const float* Wih_b  = (const float*)d_in[7];
    const float* Wix_w  = (const float*)d_in[8];
    const float* Wix_b  = (const float*)d_in[9];
    const float* bi     = (const float*)d_in[10];
    const float* WTh_b  = (const float*)d_in[12];
    const float* WTx_w  = (const float*)d_in[13];
    const float* WTx_b  = (const float*)d_in[14];
    const float* WTt_w  = (const float*)d_in[15];
    const float* WTt_b  = (const float*)d_in[16];
    const float* bT     = (const float*)d_in[17];
    const float* cls_w  = (const float*)d_in[18];
    const float* cls_b  = (const float*)d_in[19];

    prep_kernel<<<1, 64>>>(Wix_w, Wix_b, Wih_b, bi,
                           WTx_w, WTx_b, WTh_b, WTt_w, WTt_b, bT,
                           cls_w, cls_b);

    const int nrows  = in_sizes[0] / 15;
    const int blocks = nrows / ROWS_PER_CTA;     // 4096

    stgn_kernel<<<blocks, ROWS_PER_CTA>>>(X, (float*)d_out);
}